// round 1
// baseline (speedup 1.0000x reference)
#include <cuda_runtime.h>

typedef unsigned long long ull;

// ---------------- problem constants ----------------
#define F_IN  256
#define F_OUT 64
#define MAXN  100000
#define MAXE  1600000

// ---------------- scratch (no allocs allowed) ----------------
static __device__ float g_x[(size_t)MAXN * F_OUT];   // 25.6 MB
static __device__ float g_q[MAXN];
static __device__ float g_k[MAXN];
static __device__ int   g_rowptr[MAXN + 1];

// ---------------- packed f32x2 helpers (Blackwell FFMA2) ----------------
__device__ __forceinline__ ull pack2(float x, float y) {
    ull r;
    asm("mov.b64 %0, {%1, %2};" : "=l"(r) : "f"(x), "f"(y));
    return r;
}
__device__ __forceinline__ void unpack2(ull v, float &x, float &y) {
    asm("mov.b64 {%0, %1}, %2;" : "=f"(x), "=f"(y) : "l"(v));
}
__device__ __forceinline__ void ffma2(ull &d, ull a, ull b) {
    asm("fma.rn.f32x2 %0, %1, %2, %0;" : "+l"(d) : "l"(a), "l"(b));
}

// ======================================================================
// Kernel 1: x = A @ Wv     (BM=256, BN=64, BK=32, 256 threads, 8x8/thread)
// sA stored transposed [k][row] with a k-dependent xor swizzle on 8-float
// units so STS is 2-way max and inner-loop LDS.128 is conflict-free.
// ======================================================================
#define BM 256
#define BN 64
#define BK 32

__global__ void __launch_bounds__(256, 2)
gemm_kernel(const float* __restrict__ A, const float* __restrict__ W,
            float* __restrict__ X, int N)
{
    __shared__ __align__(16) float sA[BK * BM];
    __shared__ __align__(16) float sW[BK * BN];

    const int tid = threadIdx.x;
    const int bm0 = blockIdx.x * BM;
    const int rg  = tid >> 3;   // 0..31  -> rows rg*8..rg*8+7
    const int cg  = tid & 7;    // 0..7   -> cols cg*8..cg*8+7

    ull acc[8][4];
    #pragma unroll
    for (int r = 0; r < 8; r++)
        #pragma unroll
        for (int p = 0; p < 4; p++) acc[r][p] = 0ull;

    #pragma unroll 1
    for (int kk = 0; kk < F_IN; kk += BK) {
        // ---- load A tile [BM x BK], store transposed+swizzled ----
        #pragma unroll
        for (int i = 0; i < 8; i++) {
            int p  = i * 256 + tid;
            int r  = p >> 3;          // local row 0..255
            int c4 = p & 7;           // float4 index in k-chunk
            int grow = bm0 + r;
            float4 v = make_float4(0.f, 0.f, 0.f, 0.f);
            if (grow < N)
                v = *(const float4*)(A + (size_t)grow * F_IN + kk + c4 * 4);
            int sw   = ((r >> 3) ^ (c4 & 3)) << 3;         // (k>>2)&3 == c4&3
            int base = (c4 * 4) * BM + sw + (r & 7);
            sA[base         ] = v.x;
            sA[base +     BM] = v.y;
            sA[base + 2 * BM] = v.z;
            sA[base + 3 * BM] = v.w;
        }
        // ---- load W tile [BK x BN] ----
        #pragma unroll
        for (int i = 0; i < 2; i++) {
            int p  = i * 256 + tid;
            int wr = p >> 4;          // k row 0..31
            int wc = p & 15;          // float4 col 0..15
            *(float4*)(sW + wr * BN + wc * 4) =
                *(const float4*)(W + (size_t)(kk + wr) * BN + wc * 4);
        }
        __syncthreads();

        #pragma unroll 4
        for (int k = 0; k < BK; k++) {
            const float4* ap =
                (const float4*)(sA + k * BM + ((rg ^ ((k >> 2) & 3)) << 3));
            float4 alo = ap[0], ahi = ap[1];
            const float4* wp = (const float4*)(sW + k * BN + (cg << 3));
            float4 wlo = wp[0], whi = wp[1];

            ull w01 = pack2(wlo.x, wlo.y);
            ull w23 = pack2(wlo.z, wlo.w);
            ull w45 = pack2(whi.x, whi.y);
            ull w67 = pack2(whi.z, whi.w);

            float a[8] = {alo.x, alo.y, alo.z, alo.w,
                          ahi.x, ahi.y, ahi.z, ahi.w};
            #pragma unroll
            for (int r = 0; r < 8; r++) {
                ull aa = pack2(a[r], a[r]);
                ffma2(acc[r][0], aa, w01);
                ffma2(acc[r][1], aa, w23);
                ffma2(acc[r][2], aa, w45);
                ffma2(acc[r][3], aa, w67);
            }
        }
        __syncthreads();
    }

    // ---- epilogue ----
    #pragma unroll
    for (int r = 0; r < 8; r++) {
        int grow = bm0 + rg * 8 + r;
        if (grow < N) {
            float o[8];
            unpack2(acc[r][0], o[0], o[1]);
            unpack2(acc[r][1], o[2], o[3]);
            unpack2(acc[r][2], o[4], o[5]);
            unpack2(acc[r][3], o[6], o[7]);
            float* xp = X + (size_t)grow * F_OUT + cg * 8;
            *(float4*)(xp)     = make_float4(o[0], o[1], o[2], o[3]);
            *(float4*)(xp + 4) = make_float4(o[4], o[5], o[6], o[7]);
        }
    }
}

// ======================================================================
// Kernel 2: q[i] = x[i]·wq, k[i] = x[i]·wk   (warp per node)
// ======================================================================
__global__ void qk_kernel(const float* __restrict__ X,
                          const float* __restrict__ wq,
                          const float* __restrict__ wk,
                          float* __restrict__ q, float* __restrict__ k, int N)
{
    int w    = (blockIdx.x * blockDim.x + threadIdx.x) >> 5;
    int lane = threadIdx.x & 31;
    if (w >= N) return;
    float2 v = *(const float2*)(X + (size_t)w * F_OUT + lane * 2);
    float qs = v.x * __ldg(wq + 2 * lane) + v.y * __ldg(wq + 2 * lane + 1);
    float ks = v.x * __ldg(wk + 2 * lane) + v.y * __ldg(wk + 2 * lane + 1);
    #pragma unroll
    for (int off = 16; off; off >>= 1) {
        qs += __shfl_xor_sync(0xffffffffu, qs, off);
        ks += __shfl_xor_sync(0xffffffffu, ks, off);
    }
    if (lane == 0) { q[w] = qs; k[w] = ks; }
}

// ======================================================================
// Kernel 3: CSR rowptr via binary search on sorted `row`
// ======================================================================
__global__ void rowptr_kernel(const int* __restrict__ row, int N, int E)
{
    int i = blockIdx.x * blockDim.x + threadIdx.x;
    if (i > N) return;
    int lo = 0, hi = E;
    while (lo < hi) {
        int mid = (lo + hi) >> 1;
        if (__ldg(row + mid) < i) lo = mid + 1; else hi = mid;
    }
    g_rowptr[i] = lo;
}

// ======================================================================
// Kernel 4: fused segment-softmax + weighted aggregation (warp per node).
// Phase 1: online softmax (max,sum) with lanes strided over edges.
// Phase 2: lanes own 2 output features each; edges broadcast via shfl.
// No atomics anywhere.
// ======================================================================
__global__ void gat_kernel(const float* __restrict__ X,
                           const int* __restrict__ col,
                           const float* __restrict__ qv,
                           const float* __restrict__ kv,
                           const float* __restrict__ b,
                           float* __restrict__ out, int N)
{
    int w    = (blockIdx.x * blockDim.x + threadIdx.x) >> 5;
    int lane = threadIdx.x & 31;
    if (w >= N) return;

    int rp0 = g_rowptr[w];
    int rp1 = g_rowptr[w + 1];
    float qi = __ldg(qv + w);

    // ---- phase 1: online max & sum ----
    float lm = -1e30f, ls = 0.f;
    for (int e = rp0 + lane; e < rp1; e += 32) {
        int c   = __ldg(col + e);
        float a = __ldg(kv + c) + qi;
        a = (a > 0.f) ? a : 0.2f * a;
        float nm = fmaxf(lm, a);
        ls = ls * __expf(lm - nm) + __expf(a - nm);
        lm = nm;
    }
    #pragma unroll
    for (int off = 16; off; off >>= 1) {
        float om = __shfl_xor_sync(0xffffffffu, lm, off);
        float os = __shfl_xor_sync(0xffffffffu, ls, off);
        float nm = fmaxf(lm, om);
        ls = ls * __expf(lm - nm) + os * __expf(om - nm);
        lm = nm;
    }
    float m   = lm;
    float inv = (ls > 0.f) ? (1.0f / ls) : 0.f;

    // ---- phase 2: aggregate ----
    float2 acc = make_float2(0.f, 0.f);
    for (int base = rp0; base < rp1; base += 32) {
        int e = base + lane;
        int c = 0; float wgt = 0.f;
        if (e < rp1) {
            c = __ldg(col + e);
            float a = __ldg(kv + c) + qi;
            a = (a > 0.f) ? a : 0.2f * a;
            wgt = __expf(a - m) * inv;
        }
        int cnt = min(32, rp1 - base);
        for (int j = 0; j < cnt; j++) {
            float wj = __shfl_sync(0xffffffffu, wgt, j);
            int   cj = __shfl_sync(0xffffffffu, c,   j);
            float2 xv = *(const float2*)(X + (size_t)cj * F_OUT + lane * 2);
            acc.x = fmaf(wj, xv.x, acc.x);
            acc.y = fmaf(wj, xv.y, acc.y);
        }
    }

    float2 ob;
    ob.x = acc.x + __ldg(b + 2 * lane);
    ob.y = acc.y + __ldg(b + 2 * lane + 1);
    *(float2*)(out + (size_t)w * F_OUT + lane * 2) = ob;
}

// ======================================================================
// launch
// ======================================================================
extern "C" void kernel_launch(void* const* d_in, const int* in_sizes, int n_in,
                              void* d_out, int out_size)
{
    const float* A   = (const float*)d_in[0];   // node_features [N,256]
    const int*   row = (const int*)  d_in[1];   // [E] sorted
    const int*   col = (const int*)  d_in[2];   // [E]
    const float* Wv  = (const float*)d_in[3];   // [256,64]
    const float* wq  = (const float*)d_in[4];   // [64,1]
    const float* wk  = (const float*)d_in[5];   // [64,1]
    const float* b   = (const float*)d_in[6];   // [64]
    float* out = (float*)d_out;

    int N = in_sizes[0] / F_IN;
    int E = in_sizes[1];

    float* X = nullptr; float* Q = nullptr; float* K = nullptr;
    cudaGetSymbolAddress((void**)&X, g_x);
    cudaGetSymbolAddress((void**)&Q, g_q);
    cudaGetSymbolAddress((void**)&K, g_k);

    // 1) x = A @ Wv
    gemm_kernel<<<(N + BM - 1) / BM, 256>>>(A, Wv, X, N);

    // 2) q, k
    int warpBlocks = (N * 32 + 255) / 256;
    qk_kernel<<<warpBlocks, 256>>>(X, wq, wk, Q, K, N);

    // 3) rowptr
    rowptr_kernel<<<(N + 1 + 255) / 256, 256>>>(row, N, E);

    // 4) fused softmax + aggregation
    gat_kernel<<<warpBlocks, 256>>>(X, col, Q, K, b, out, N);
}

// round 5
// speedup vs baseline: 1.2645x; 1.2645x over previous
#include <cuda_runtime.h>
#include <cuda_bf16.h>

typedef unsigned int uint;

// ---------------- problem constants ----------------
#define F_IN  256
#define F_OUT 64
#define MAXN  100000

// ---------------- scratch (no allocs allowed) ----------------
static __device__ float g_x[(size_t)MAXN * F_OUT];   // 25.6 MB
static __device__ float g_q[MAXN];
static __device__ float g_k[MAXN];
static __device__ int   g_rowptr[MAXN + 1];
// W hi/lo planes, transposed: [plane][n(64)][k(256)] bf16  (64 KB)
static __device__ __align__(16) unsigned short g_wt[2 * 64 * 256];

// ======================================================================
// Kernel 1: rowptr (binary search on sorted row) + W hi/lo split+transpose
// ======================================================================
__global__ void prep_kernel(const int* __restrict__ row,
                            const float* __restrict__ W, int N, int E)
{
    if (blockIdx.x == gridDim.x - 1) {
        for (int idx = threadIdx.x; idx < F_IN * F_OUT; idx += blockDim.x) {
            int k = idx >> 6;        // 0..255
            int n = idx & 63;        // 0..63
            float w = __ldg(W + idx);
            unsigned short hb, lb;
            asm("cvt.rn.bf16.f32 %0, %1;" : "=h"(hb) : "f"(w));
            float hf = __uint_as_float(((uint)hb) << 16);
            float lo = w - hf;
            asm("cvt.rn.bf16.f32 %0, %1;" : "=h"(lb) : "f"(lo));
            g_wt[n * 256 + k]                 = hb;   // hi plane
            g_wt[64 * 256 + n * 256 + k]      = lb;   // lo plane
        }
        return;
    }
    int i = blockIdx.x * blockDim.x + threadIdx.x;
    if (i > N) return;
    int lo = 0, hi = E;
    while (lo < hi) {
        int mid = (lo + hi) >> 1;
        if (__ldg(row + mid) < i) lo = mid + 1; else hi = mid;
    }
    g_rowptr[i] = lo;
}

// ======================================================================
// Kernel 2: X = A @ Wv via mma.sync m16n8k16 bf16 (hi/lo split, 3 terms),
// fused q/k epilogue.  A: global->registers in fragment layout (no smem).
// W: smem, transposed [n][k] with 264-elem row pad (conflict-free LDS).
// CTA: 256 threads = 8 warps, warp tile 32x64, CTA tile 256x64.
// ======================================================================
#define WT_STRIDE 264                 // bf16 elems per padded row
#define WT_PLANE  (64 * WT_STRIDE)    // 16896 elems
#define SMEM_WQ   (2 * WT_PLANE * 2)          // byte offset of wq
#define SMEM_WK   (SMEM_WQ + 256)
#define GEMM_DSMEM (SMEM_WK + 256)            // 68096 bytes

#define MMA16816(d, a, b0, b1)                                              \
    asm volatile("mma.sync.aligned.m16n8k16.row.col.f32.bf16.bf16.f32 "     \
                 "{%0,%1,%2,%3}, {%4,%5,%6,%7}, {%8,%9}, {%0,%1,%2,%3};"    \
                 : "+f"((d)[0]), "+f"((d)[1]), "+f"((d)[2]), "+f"((d)[3])   \
                 : "r"((a)[0]), "r"((a)[1]), "r"((a)[2]), "r"((a)[3]),      \
                   "r"(b0), "r"(b1))

__device__ __forceinline__ void split2(float2 v, uint &hi, uint &lo)
{
    asm("cvt.rn.bf16x2.f32 %0, %1, %2;" : "=r"(hi) : "f"(v.y), "f"(v.x));
    float rx = v.x - __uint_as_float(hi << 16);
    float ry = v.y - __uint_as_float(hi & 0xffff0000u);
    asm("cvt.rn.bf16x2.f32 %0, %1, %2;" : "=r"(lo) : "f"(ry), "f"(rx));
}

__global__ void __launch_bounds__(256, 2)
gemm_mma_kernel(const float* __restrict__ A,
                const float* __restrict__ wq, const float* __restrict__ wk,
                float* __restrict__ X, int N)
{
    extern __shared__ __align__(16) char sm[];
    unsigned short* sWt = (unsigned short*)sm;

    const int tid  = threadIdx.x;
    const int wid  = tid >> 5;
    const int lane = tid & 31;
    const int lr   = lane >> 2;   // 0..7
    const int lc   = lane & 3;    // 0..3
    const int m0   = blockIdx.x * 256 + wid * 32;

    // ---- stage W planes into padded smem + wq/wk ----
    {
        const uint4* src = (const uint4*)g_wt;     // 4096 uint4
        uint4* dst = (uint4*)sm;
        #pragma unroll
        for (int i = 0; i < 16; i++) {
            int p     = i * 256 + tid;
            int plane = p >> 11;         // 2048 uint4 per plane
            int rem   = p & 2047;
            int n     = rem >> 5;        // 32 uint4 per source row
            int kc    = rem & 31;
            dst[plane * (64 * 33) + n * 33 + kc] = src[p];
        }
        if (tid < 64) {
            ((float*)(sm + SMEM_WQ))[tid] = __ldg(wq + tid);
            ((float*)(sm + SMEM_WK))[tid] = __ldg(wk + tid);
        }
    }
    __syncthreads();

    float acc[2][8][4];
    #pragma unroll
    for (int mt = 0; mt < 2; mt++)
        #pragma unroll
        for (int nt = 0; nt < 8; nt++)
            #pragma unroll
            for (int i = 0; i < 4; i++) acc[mt][nt][i] = 0.f;

    const float2 z2 = make_float2(0.f, 0.f);

    #pragma unroll 1
    for (int ks = 0; ks < 16; ks++) {
        const int k0 = ks * 16;
        uint ah[2][4], al[2][4];
        // ---- A fragments straight from global, hi/lo split ----
        #pragma unroll
        for (int mt = 0; mt < 2; mt++) {
            int r0 = m0 + mt * 16 + lr;
            int r1 = r0 + 8;
            const float* p0 = A + (size_t)r0 * F_IN + k0 + lc * 2;
            const float* p1 = A + (size_t)r1 * F_IN + k0 + lc * 2;
            float2 v0 = (r0 < N) ? *(const float2*)(p0)     : z2;
            float2 v1 = (r1 < N) ? *(const float2*)(p1)     : z2;
            float2 v2 = (r0 < N) ? *(const float2*)(p0 + 8) : z2;
            float2 v3 = (r1 < N) ? *(const float2*)(p1 + 8) : z2;
            split2(v0, ah[mt][0], al[mt][0]);
            split2(v1, ah[mt][1], al[mt][1]);
            split2(v2, ah[mt][2], al[mt][2]);
            split2(v3, ah[mt][3], al[mt][3]);
        }
        // ---- per n-tile: B frags from smem, 6 mma ----
        #pragma unroll
        for (int nt = 0; nt < 8; nt++) {
            const unsigned short* wp =
                sWt + (nt * 8 + lr) * WT_STRIDE + k0 + lc * 2;
            uint bh0 = *(const uint*)(wp);
            uint bh1 = *(const uint*)(wp + 8);
            uint bl0 = *(const uint*)(wp + WT_PLANE);
            uint bl1 = *(const uint*)(wp + WT_PLANE + 8);
            #pragma unroll
            for (int mt = 0; mt < 2; mt++) {
                MMA16816(acc[mt][nt], ah[mt], bh0, bh1);
                MMA16816(acc[mt][nt], al[mt], bh0, bh1);
                MMA16816(acc[mt][nt], ah[mt], bl0, bl1);
            }
        }
    }

    // ---- epilogue: store X, fused q/k ----
    const float* swq = (const float*)(sm + SMEM_WQ);
    const float* swk = (const float*)(sm + SMEM_WK);
    #pragma unroll
    for (int mt = 0; mt < 2; mt++) {
        #pragma unroll
        for (int h = 0; h < 2; h++) {
            int row = m0 + mt * 16 + lr + h * 8;
            float qa = 0.f, ka = 0.f;
            if (row < N) {
                float* xp = X + (size_t)row * F_OUT;
                #pragma unroll
                for (int nt = 0; nt < 8; nt++) {
                    float c0 = acc[mt][nt][h * 2];
                    float c1 = acc[mt][nt][h * 2 + 1];
                    int colb = nt * 8 + lc * 2;
                    *(float2*)(xp + colb) = make_float2(c0, c1);
                    qa += c0 * swq[colb] + c1 * swq[colb + 1];
                    ka += c0 * swk[colb] + c1 * swk[colb + 1];
                }
            }
            qa += __shfl_xor_sync(0xffffffffu, qa, 1);
            qa += __shfl_xor_sync(0xffffffffu, qa, 2);
            ka += __shfl_xor_sync(0xffffffffu, ka, 1);
            ka += __shfl_xor_sync(0xffffffffu, ka, 2);
            if (lc == 0 && row < N) { g_q[row] = qa; g_k[row] = ka; }
        }
    }
}

// ======================================================================
// Kernel 3: fused segment-softmax + aggregation (warp per node).
// deg<=32 fast path: col/logit cached in registers from phase 1.
// Normalization deferred to the final accumulator.
// ======================================================================
__global__ void gat_kernel(const float* __restrict__ X,
                           const int* __restrict__ col,
                           const float* __restrict__ qv,
                           const float* __restrict__ kv,
                           const float* __restrict__ b,
                           float* __restrict__ out, int N)
{
    int w    = (blockIdx.x * blockDim.x + threadIdx.x) >> 5;
    int lane = threadIdx.x & 31;
    if (w >= N) return;

    int rp0 = g_rowptr[w];
    int rp1 = g_rowptr[w + 1];
    int deg = rp1 - rp0;
    float qi = __ldg(qv + w);

    // ---- phase 1: online max & sum (cache first edge per lane) ----
    float lm = -1e30f, ls = 0.f;
    int   cc = 0;
    float aa = 0.f;
    int e0 = rp0 + lane;
    if (e0 < rp1) {
        cc = __ldg(col + e0);
        float a = __ldg(kv + cc) + qi;
        a  = (a > 0.f) ? a : 0.2f * a;
        aa = a; lm = a; ls = 1.f;
    }
    for (int e = e0 + 32; e < rp1; e += 32) {
        int c   = __ldg(col + e);
        float a = __ldg(kv + c) + qi;
        a = (a > 0.f) ? a : 0.2f * a;
        float nm = fmaxf(lm, a);
        ls = ls * __expf(lm - nm) + __expf(a - nm);
        lm = nm;
    }
    #pragma unroll
    for (int off = 16; off; off >>= 1) {
        float om = __shfl_xor_sync(0xffffffffu, lm, off);
        float os = __shfl_xor_sync(0xffffffffu, ls, off);
        float nm = fmaxf(lm, om);
        ls = ls * __expf(lm - nm) + os * __expf(om - nm);
        lm = nm;
    }
    float m   = lm;
    float inv = (ls > 0.f) ? (1.0f / ls) : 0.f;

    // ---- phase 2: half-warp per edge, float4 per lane ----
    int half = lane >> 4;          // 0 or 1
    int fi   = lane & 15;          // float4 index within 64 features
    float4 acc = make_float4(0.f, 0.f, 0.f, 0.f);

    if (deg <= 32) {
        float wgt = (lane < deg) ? __expf(aa - m) : 0.f;
        for (int j = 0; j < deg; j += 2) {
            int jj   = j + half;
            float wj = __shfl_sync(0xffffffffu, wgt, jj);
            int   cj = __shfl_sync(0xffffffffu, cc,  jj);
            if (jj < deg) {
                float4 xv = *(const float4*)(X + (size_t)cj * F_OUT + fi * 4);
                acc.x = fmaf(wj, xv.x, acc.x);
                acc.y = fmaf(wj, xv.y, acc.y);
                acc.z = fmaf(wj, xv.z, acc.z);
                acc.w = fmaf(wj, xv.w, acc.w);
            }
        }
    } else {
        for (int base = rp0; base < rp1; base += 32) {
            int e = base + lane;
            int c = 0; float wgt = 0.f;
            if (e < rp1) {
                c = __ldg(col + e);
                float a = __ldg(kv + c) + qi;
                a = (a > 0.f) ? a : 0.2f * a;
                wgt = __expf(a - m);
            }
            int cnt = min(32, rp1 - base);
            for (int j = 0; j < cnt; j += 2) {
                int jj   = j + half;
                float wj = __shfl_sync(0xffffffffu, wgt, jj);
                int   cj = __shfl_sync(0xffffffffu, c,   jj);
                if (jj < cnt) {
                    float4 xv = *(const float4*)(X + (size_t)cj * F_OUT + fi * 4);
                    acc.x = fmaf(wj, xv.x, acc.x);
                    acc.y = fmaf(wj, xv.y, acc.y);
                    acc.z = fmaf(wj, xv.z, acc.z);
                    acc.w = fmaf(wj, xv.w, acc.w);
                }
            }
        }
    }

    acc.x += __shfl_xor_sync(0xffffffffu, acc.x, 16);
    acc.y += __shfl_xor_sync(0xffffffffu, acc.y, 16);
    acc.z += __shfl_xor_sync(0xffffffffu, acc.z, 16);
    acc.w += __shfl_xor_sync(0xffffffffu, acc.w, 16);

    if (lane < 16) {
        float4 bb = *(const float4*)(b + fi * 4);
        float4 o  = make_float4(fmaf(acc.x, inv, bb.x),
                                fmaf(acc.y, inv, bb.y),
                                fmaf(acc.z, inv, bb.z),
                                fmaf(acc.w, inv, bb.w));
        *(float4*)(out + (size_t)w * F_OUT + fi * 4) = o;
    }
}

// ======================================================================
// launch
// ======================================================================
extern "C" void kernel_launch(void* const* d_in, const int* in_sizes, int n_in,
                              void* d_out, int out_size)
{
    const float* A   = (const float*)d_in[0];   // node_features [N,256]
    const int*   row = (const int*)  d_in[1];   // [E] sorted
    const int*   col = (const int*)  d_in[2];   // [E]
    const float* Wv  = (const float*)d_in[3];   // [256,64]
    const float* wq  = (const float*)d_in[4];   // [64,1]
    const float* wk  = (const float*)d_in[5];   // [64,1]
    const float* b   = (const float*)d_in[6];   // [64]
    float* out = (float*)d_out;

    int N = in_sizes[0] / F_IN;
    int E = in_sizes[1];

    float* X = nullptr; float* Q = nullptr; float* K = nullptr;
    cudaGetSymbolAddress((void**)&X, g_x);
    cudaGetSymbolAddress((void**)&Q, g_q);
    cudaGetSymbolAddress((void**)&K, g_k);

    cudaFuncSetAttribute(gemm_mma_kernel,
                         cudaFuncAttributeMaxDynamicSharedMemorySize, GEMM_DSMEM);

    // 1) rowptr + W staging
    int prepBlocks = (N + 1 + 255) / 256 + 1;
    prep_kernel<<<prepBlocks, 256>>>(row, Wv, N, E);

    // 2) X = A @ Wv (mma.sync bf16 hi/lo), fused q/k epilogue
    gemm_mma_kernel<<<(N + 255) / 256, 256, GEMM_DSMEM>>>(A, wq, wk, X, N);

    // 3) fused softmax + aggregation
    int warpBlocks = (N * 32 + 255) / 256;
    gat_kernel<<<warpBlocks, 256>>>(X, col, Q, K, b, out, N);
}